// round 1
// baseline (speedup 1.0000x reference)
#include <cuda_runtime.h>
#include <math.h>

#define EPSV 1e-5f
#define NQ 12
#define B 1024
#define S 1024

// Scratch tables (device globals: allocation-free, graph-capturable)
__device__ __align__(16) float g_attn[S * NQ];
__device__ __align__(16) float g_ffn[S * NQ];

// -------------------------------------------------------------------------
// Kernel 1: attn[s, w]
//   z_i = cos(rx_i) * cos(x[s, i, 0])     (analytic <Z> of RX*RY product state)
//   CNOT chain(0->1..10->11) + ring CNOT(11->0) => bit w of output is XOR of
//   original bits {0..w} (w>=1) and {1..11} (w=0); independent bits =>
//   attn[s,w] = prod_{i in S_w} z_i.
// -------------------------------------------------------------------------
__global__ void k_attn(const float* __restrict__ x, const float* __restrict__ rx)
{
    int s = blockIdx.x * blockDim.x + threadIdx.x;
    if (s >= S) return;

    double z[NQ];
#pragma unroll
    for (int i = 0; i < NQ; i++) {
        double t = (double)x[((size_t)s * S + i) * NQ];   // x[s, i, 0]
        z[i] = cos((double)rx[i]) * cos(t);
    }

    double p = z[0];
#pragma unroll
    for (int w = 1; w < NQ; w++) {
        p *= z[w];
        g_attn[s * NQ + w] = (float)p;
    }
    double q = z[1];
#pragma unroll
    for (int i = 2; i < NQ; i++) q *= z[i];
    g_attn[s * NQ + 0] = (float)q;
}

// -------------------------------------------------------------------------
// Kernel 2: ffn[b, :]
//   tok2[b,i] = LN1(x[b,i,:] + attn[i,:])[0]
//   m_i = cos(ry_i + tok2_i)   (RY(ry)RY(tok2)|0> product state, no CNOTs)
//   ffn[b,e] = sum_i relu(m_i) * w_ffn[e,i] + b_ffn[e]
// -------------------------------------------------------------------------
__global__ void k_ffn(const float* __restrict__ x, const float* __restrict__ ry,
                      const float* __restrict__ w_ffn, const float* __restrict__ b_ffn,
                      const float* __restrict__ ln1g, const float* __restrict__ ln1b)
{
    int b = blockIdx.x * blockDim.x + threadIdx.x;
    if (b >= B) return;

    float acc[NQ];
#pragma unroll
    for (int e = 0; e < NQ; e++) acc[e] = __ldg(&b_ffn[e]);

    float g0 = __ldg(&ln1g[0]);
    float bb0 = __ldg(&ln1b[0]);

#pragma unroll
    for (int i = 0; i < NQ; i++) {
        float v[NQ];
        float mu = 0.f;
#pragma unroll
        for (int e = 0; e < NQ; e++) {
            v[e] = x[((size_t)b * S + i) * NQ + e] + g_attn[i * NQ + e];
            mu += v[e];
        }
        mu *= (1.f / 12.f);
        float var = 0.f;
#pragma unroll
        for (int e = 0; e < NQ; e++) {
            float d = v[e] - mu;
            var += d * d;
        }
        var *= (1.f / 12.f);
        float tok2 = (v[0] - mu) * rsqrtf(var + EPSV) * g0 + bb0;
        double m = cos((double)__ldg(&ry[i]) + (double)tok2);
        float r = (m > 0.0) ? (float)m : 0.f;
#pragma unroll
        for (int e = 0; e < NQ; e++) acc[e] = fmaf(r, __ldg(&w_ffn[e * NQ + i]), acc[e]);
    }
#pragma unroll
    for (int e = 0; e < NQ; e++) g_ffn[b * NQ + e] = acc[e];
}

// -------------------------------------------------------------------------
// Kernel 3 (the bandwidth pass):
//   out[b,s,:] = LN2( LN1(x[b,s,:] + attn[s,:]) + ffn[s,:] )
// One row (12 floats = 3x float4) per thread. Block covers 256 consecutive
// rows => 256 consecutive s (256 | 1024), so attn/ffn slices are staged in
// shared memory once per block.
// -------------------------------------------------------------------------
__global__ void __launch_bounds__(256) k_main(
    const float* __restrict__ x,
    const float* __restrict__ ln1g, const float* __restrict__ ln1b,
    const float* __restrict__ ln2g, const float* __restrict__ ln2b,
    float* __restrict__ out)
{
    __shared__ __align__(16) float s_attn[256 * NQ];
    __shared__ __align__(16) float s_ffn[256 * NQ];
    __shared__ float s_g1[NQ], s_b1[NQ], s_g2[NQ], s_b2[NQ];

    int row0 = blockIdx.x * 256;
    int s0 = row0 & (S - 1);

    // Cooperative stage of attn/ffn slices (768 float4 each)
    {
        const float4* ap = (const float4*)(g_attn + s0 * NQ);
        const float4* fp = (const float4*)(g_ffn + s0 * NQ);
        float4* sa = (float4*)s_attn;
        float4* sf = (float4*)s_ffn;
#pragma unroll
        for (int k = 0; k < 3; k++) {
            int i = threadIdx.x + k * 256;
            sa[i] = ap[i];
            sf[i] = fp[i];
        }
    }
    if (threadIdx.x < NQ) {
        s_g1[threadIdx.x] = ln1g[threadIdx.x];
        s_b1[threadIdx.x] = ln1b[threadIdx.x];
        s_g2[threadIdx.x] = ln2g[threadIdx.x];
        s_b2[threadIdx.x] = ln2b[threadIdx.x];
    }
    __syncthreads();

    size_t row = (size_t)row0 + threadIdx.x;
    const float4* xp = (const float4*)(x + row * NQ);
    float4 a0 = xp[0], a1 = xp[1], a2 = xp[2];

    int ls = threadIdx.x;
    const float4* av = (const float4*)(s_attn + ls * NQ);
    float4 t0 = av[0], t1 = av[1], t2 = av[2];
    const float4* fv = (const float4*)(s_ffn + ls * NQ);
    float4 f0 = fv[0], f1 = fv[1], f2 = fv[2];

    float v[NQ];
    v[0] = a0.x + t0.x; v[1] = a0.y + t0.y; v[2]  = a0.z + t0.z; v[3]  = a0.w + t0.w;
    v[4] = a1.x + t1.x; v[5] = a1.y + t1.y; v[6]  = a1.z + t1.z; v[7]  = a1.w + t1.w;
    v[8] = a2.x + t2.x; v[9] = a2.y + t2.y; v[10] = a2.z + t2.z; v[11] = a2.w + t2.w;

    // LN1
    float mu = 0.f;
#pragma unroll
    for (int e = 0; e < NQ; e++) mu += v[e];
    mu *= (1.f / 12.f);
    float var = 0.f;
#pragma unroll
    for (int e = 0; e < NQ; e++) { float d = v[e] - mu; var += d * d; }
    var *= (1.f / 12.f);
    float rs = rsqrtf(var + EPSV);

    float fa[NQ];
    fa[0] = f0.x; fa[1] = f0.y; fa[2]  = f0.z; fa[3]  = f0.w;
    fa[4] = f1.x; fa[5] = f1.y; fa[6]  = f1.z; fa[7]  = f1.w;
    fa[8] = f2.x; fa[9] = f2.y; fa[10] = f2.z; fa[11] = f2.w;

    float u[NQ];
#pragma unroll
    for (int e = 0; e < NQ; e++)
        u[e] = (v[e] - mu) * rs * s_g1[e] + s_b1[e] + fa[e];

    // LN2
    float mu2 = 0.f;
#pragma unroll
    for (int e = 0; e < NQ; e++) mu2 += u[e];
    mu2 *= (1.f / 12.f);
    float var2 = 0.f;
#pragma unroll
    for (int e = 0; e < NQ; e++) { float d = u[e] - mu2; var2 += d * d; }
    var2 *= (1.f / 12.f);
    float rs2 = rsqrtf(var2 + EPSV);

    float o[NQ];
#pragma unroll
    for (int e = 0; e < NQ; e++)
        o[e] = (u[e] - mu2) * rs2 * s_g2[e] + s_b2[e];

    float4* op = (float4*)(out + row * NQ);
    op[0] = make_float4(o[0], o[1], o[2],  o[3]);
    op[1] = make_float4(o[4], o[5], o[6],  o[7]);
    op[2] = make_float4(o[8], o[9], o[10], o[11]);
}

// -------------------------------------------------------------------------
extern "C" void kernel_launch(void* const* d_in, const int* in_sizes, int n_in,
                              void* d_out, int out_size)
{
    const float* x     = (const float*)d_in[0];
    const float* rx    = (const float*)d_in[1];
    const float* ry    = (const float*)d_in[2];
    const float* w_ffn = (const float*)d_in[3];
    const float* b_ffn = (const float*)d_in[4];
    const float* g1    = (const float*)d_in[5];
    const float* b1    = (const float*)d_in[6];
    const float* g2    = (const float*)d_in[7];
    const float* b2    = (const float*)d_in[8];
    float* out = (float*)d_out;

    k_attn<<<4, 256>>>(x, rx);
    k_ffn<<<4, 256>>>(x, ry, w_ffn, b_ffn, g1, b1);
    k_main<<<(B * S) / 256, 256>>>(x, g1, b1, g2, b2, out);
}

// round 2
// speedup vs baseline: 1.1307x; 1.1307x over previous
#include <cuda_runtime.h>
#include <math.h>

#define EPSV 1e-5f
#define NQ 12
#define B 1024
#define S 1024
#define BPB 8            // batch rows processed per block in k_main

// Scratch tables (device globals: allocation-free, graph-capturable)
__device__ __align__(16) float g_attn[S * NQ];
__device__ __align__(16) float g_ffn[S * NQ];

// -------------------------------------------------------------------------
// Prep kernel: builds both tables in one launch, all float math.
//
// attn[s,w]:
//   z_i = cosf(rx_i) * cosf(x[s,i,0])   (analytic <Z> of RX*RY product state)
//   CNOT chain + ring CNOT => attn[s,w] = prod_{i in S_w} z_i with
//   S_w = {0..w} for w>=1, S_0 = {1..11}.
//
// ffn[b,:]:
//   tok2[b,i] = LN1(x[b,i,:] + attn[i,:])[0]   (only attn rows 0..11 needed!)
//   m_i = cosf(ry_i + tok2_i)                  (RY∘RY stays product state)
//   ffn[b,e] = sum_i relu(m_i) * w_ffn[e,i] + b_ffn[e]
// -------------------------------------------------------------------------
__global__ void __launch_bounds__(256) k_prep(
    const float* __restrict__ x,  const float* __restrict__ rx,
    const float* __restrict__ ry, const float* __restrict__ w_ffn,
    const float* __restrict__ b_ffn,
    const float* __restrict__ ln1g, const float* __restrict__ ln1b)
{
    __shared__ float sm_attn[NQ * NQ];   // attn rows 0..11 (for phase B)

    int s = blockIdx.x * 256 + threadIdx.x;

    float cr[NQ];
#pragma unroll
    for (int i = 0; i < NQ; i++) cr[i] = cosf(__ldg(&rx[i]));

    // ---- Phase A: attn row s ----
    float z[NQ];
#pragma unroll
    for (int i = 0; i < NQ; i++)
        z[i] = cr[i] * cosf(__ldg(&x[((size_t)s * S + i) * NQ]));

    {
        float p = z[0];
#pragma unroll
        for (int w = 1; w < NQ; w++) {
            p *= z[w];
            g_attn[s * NQ + w] = p;
        }
        float q = z[1];
#pragma unroll
        for (int i = 2; i < NQ; i++) q *= z[i];
        g_attn[s * NQ + 0] = q;
    }

    // Threads 0..11 (re)compute attn rows 0..11 into smem for phase B
    if (threadIdx.x < NQ) {
        int i = threadIdx.x;
        float zz[NQ];
#pragma unroll
        for (int j = 0; j < NQ; j++)
            zz[j] = cr[j] * cosf(__ldg(&x[((size_t)i * S + j) * NQ]));
        float p = zz[0];
#pragma unroll
        for (int w = 1; w < NQ; w++) {
            p *= zz[w];
            sm_attn[i * NQ + w] = p;
        }
        float q = zz[1];
#pragma unroll
        for (int j = 2; j < NQ; j++) q *= zz[j];
        sm_attn[i * NQ + 0] = q;
    }
    __syncthreads();

    // ---- Phase B: ffn row b (= s) ----
    int b = s;
    float acc[NQ];
#pragma unroll
    for (int e = 0; e < NQ; e++) acc[e] = __ldg(&b_ffn[e]);

    float g0  = __ldg(&ln1g[0]);
    float bb0 = __ldg(&ln1b[0]);

#pragma unroll
    for (int i = 0; i < NQ; i++) {
        float v[NQ];
        float mu = 0.f;
#pragma unroll
        for (int e = 0; e < NQ; e++) {
            v[e] = __ldg(&x[((size_t)b * S + i) * NQ + e]) + sm_attn[i * NQ + e];
            mu += v[e];
        }
        mu *= (1.f / 12.f);
        float var = 0.f;
#pragma unroll
        for (int e = 0; e < NQ; e++) {
            float d = v[e] - mu;
            var += d * d;
        }
        var *= (1.f / 12.f);
        float tok2 = (v[0] - mu) * rsqrtf(var + EPSV) * g0 + bb0;
        float m = cosf(__ldg(&ry[i]) + tok2);
        float r = fmaxf(m, 0.f);
#pragma unroll
        for (int e = 0; e < NQ; e++)
            acc[e] = fmaf(r, __ldg(&w_ffn[e * NQ + i]), acc[e]);
    }
#pragma unroll
    for (int e = 0; e < NQ; e++) g_ffn[b * NQ + e] = acc[e];
}

// -------------------------------------------------------------------------
// Main bandwidth pass:
//   out[b,s,:] = LN2( LN1(x[b,s,:] + attn[s,:]) + ffn[s,:] )
// grid = (S/256, B/BPB). Each block stages one 256-wide s-window of the
// attn/ffn tables in smem ONCE, then sweeps BPB batch rows over it:
// table L2 traffic drops from 96MB (R1) to 12MB.
// -------------------------------------------------------------------------
__global__ void __launch_bounds__(256) k_main(
    const float* __restrict__ x,
    const float* __restrict__ ln1g, const float* __restrict__ ln1b,
    const float* __restrict__ ln2g, const float* __restrict__ ln2b,
    float* __restrict__ out)
{
    __shared__ __align__(16) float s_attn[256 * NQ];
    __shared__ __align__(16) float s_ffn[256 * NQ];
    __shared__ float s_g1[NQ], s_b1[NQ], s_g2[NQ], s_b2[NQ];

    int s0 = blockIdx.x * 256;
    int b0 = blockIdx.y * BPB;

    // Stage tables (768 float4 each)
    {
        const float4* ap = (const float4*)(g_attn + s0 * NQ);
        const float4* fp = (const float4*)(g_ffn + s0 * NQ);
        float4* sa = (float4*)s_attn;
        float4* sf = (float4*)s_ffn;
#pragma unroll
        for (int k = 0; k < 3; k++) {
            int i = threadIdx.x + k * 256;
            sa[i] = ap[i];
            sf[i] = fp[i];
        }
    }
    if (threadIdx.x < NQ) {
        s_g1[threadIdx.x] = ln1g[threadIdx.x];
        s_b1[threadIdx.x] = ln1b[threadIdx.x];
        s_g2[threadIdx.x] = ln2g[threadIdx.x];
        s_b2[threadIdx.x] = ln2b[threadIdx.x];
    }
    __syncthreads();

    // Loop-invariant per-thread table values -> registers
    int ls = threadIdx.x;
    const float4* av = (const float4*)(s_attn + ls * NQ);
    float4 t0 = av[0], t1 = av[1], t2 = av[2];
    const float4* fv = (const float4*)(s_ffn + ls * NQ);
    float4 f0 = fv[0], f1 = fv[1], f2 = fv[2];

    float ta[NQ];
    ta[0] = t0.x; ta[1] = t0.y; ta[2]  = t0.z; ta[3]  = t0.w;
    ta[4] = t1.x; ta[5] = t1.y; ta[6]  = t1.z; ta[7]  = t1.w;
    ta[8] = t2.x; ta[9] = t2.y; ta[10] = t2.z; ta[11] = t2.w;
    float fa[NQ];
    fa[0] = f0.x; fa[1] = f0.y; fa[2]  = f0.z; fa[3]  = f0.w;
    fa[4] = f1.x; fa[5] = f1.y; fa[6]  = f1.z; fa[7]  = f1.w;
    fa[8] = f2.x; fa[9] = f2.y; fa[10] = f2.z; fa[11] = f2.w;

    float g1[NQ], b1[NQ], g2[NQ], b2[NQ];
#pragma unroll
    for (int e = 0; e < NQ; e++) {
        g1[e] = s_g1[e]; b1[e] = s_b1[e];
        g2[e] = s_g2[e]; b2[e] = s_b2[e];
    }

#pragma unroll
    for (int it = 0; it < BPB; it++) {
        size_t row = (size_t)(b0 + it) * S + s0 + threadIdx.x;
        const float4* xp = (const float4*)(x + row * NQ);
        float4 a0 = xp[0], a1 = xp[1], a2 = xp[2];

        float v[NQ];
        v[0] = a0.x + ta[0]; v[1] = a0.y + ta[1]; v[2]  = a0.z + ta[2];  v[3]  = a0.w + ta[3];
        v[4] = a1.x + ta[4]; v[5] = a1.y + ta[5]; v[6]  = a1.z + ta[6];  v[7]  = a1.w + ta[7];
        v[8] = a2.x + ta[8]; v[9] = a2.y + ta[9]; v[10] = a2.z + ta[10]; v[11] = a2.w + ta[11];

        // LN1
        float mu = 0.f;
#pragma unroll
        for (int e = 0; e < NQ; e++) mu += v[e];
        mu *= (1.f / 12.f);
        float var = 0.f;
#pragma unroll
        for (int e = 0; e < NQ; e++) { float d = v[e] - mu; var += d * d; }
        var *= (1.f / 12.f);
        float rs = rsqrtf(var + EPSV);

        float u[NQ];
#pragma unroll
        for (int e = 0; e < NQ; e++)
            u[e] = (v[e] - mu) * rs * g1[e] + b1[e] + fa[e];

        // LN2
        float mu2 = 0.f;
#pragma unroll
        for (int e = 0; e < NQ; e++) mu2 += u[e];
        mu2 *= (1.f / 12.f);
        float var2 = 0.f;
#pragma unroll
        for (int e = 0; e < NQ; e++) { float d = u[e] - mu2; var2 += d * d; }
        var2 *= (1.f / 12.f);
        float rs2 = rsqrtf(var2 + EPSV);

        float o[NQ];
#pragma unroll
        for (int e = 0; e < NQ; e++)
            o[e] = (u[e] - mu2) * rs2 * g2[e] + b2[e];

        float4* op = (float4*)(out + row * NQ);
        op[0] = make_float4(o[0], o[1], o[2],  o[3]);
        op[1] = make_float4(o[4], o[5], o[6],  o[7]);
        op[2] = make_float4(o[8], o[9], o[10], o[11]);
    }
}

// -------------------------------------------------------------------------
extern "C" void kernel_launch(void* const* d_in, const int* in_sizes, int n_in,
                              void* d_out, int out_size)
{
    const float* x     = (const float*)d_in[0];
    const float* rx    = (const float*)d_in[1];
    const float* ry    = (const float*)d_in[2];
    const float* w_ffn = (const float*)d_in[3];
    const float* b_ffn = (const float*)d_in[4];
    const float* g1    = (const float*)d_in[5];
    const float* b1    = (const float*)d_in[6];
    const float* g2    = (const float*)d_in[7];
    const float* b2    = (const float*)d_in[8];
    float* out = (float*)d_out;

    k_prep<<<S / 256, 256>>>(x, rx, ry, w_ffn, b_ffn, g1, b1);

    dim3 grid(S / 256, B / BPB);
    k_main<<<grid, 256>>>(x, g1, b1, g2, b2, out);
}

// round 4
// speedup vs baseline: 2.1578x; 1.9084x over previous
#include <cuda_runtime.h>
#include <math.h>

#define EPSV 1e-5f
#define NQ 12
#define B 1024
#define S 1024
#define RPB 16                 // rows per block in k_prep
#define PREP_T (RPB * NQ)      // 192 threads
#define BPB 4                  // batch rows per block in k_main

__device__ __align__(16) float g_attn[S * NQ];
__device__ __align__(16) float g_ffn[S * NQ];

// -------------------------------------------------------------------------
// k_prep: builds attn + ffn tables. One thread per (row, qubit) pair.
// All x data needed per row s is the contiguous 576B chunk x[s, 0:12, 0:12];
// staged into smem with coalesced float4 loads.
//
// attn[s,w]: z_i = cos(rx_i)*cos(x[s,i,0]); CNOT chain + ring =>
//   attn[s,w] = prod_{i in S_w} z_i,  S_w = {0..w} (w>=1), S_0 = {1..11}.
// ffn[b,:]:  tok2[b,i] = LN1(x[b,i,:]+attn[i,:])[0];
//   ffn[b,e] = sum_i relu(cos(ry_i+tok2_i)) * w_ffn[e,i] + b_ffn[e]
// -------------------------------------------------------------------------
__global__ void __launch_bounds__(PREP_T) k_prep(
    const float* __restrict__ x,  const float* __restrict__ rx,
    const float* __restrict__ ry, const float* __restrict__ w_ffn,
    const float* __restrict__ b_ffn,
    const float* __restrict__ ln1g, const float* __restrict__ ln1b)
{
    __shared__ __align__(16) float sm_x[RPB * 144];  // x[s0+r, 0:12, 0:12]
    __shared__ float sm_z[RPB][NQ];                  // z_i per row
    __shared__ float sm_z0[NQ * NQ];                 // z for global rows 0..11
    __shared__ float sm_attn0[NQ * NQ];              // attn rows 0..11
    __shared__ float sm_w[NQ * NQ];                  // w_ffn [e,i]
    __shared__ float sm_r[RPB][NQ];                  // relu(cos(ry+tok2))
    __shared__ float sm_cr[NQ], sm_ry[NQ], sm_bf[NQ];

    int tid = threadIdx.x;
    int s0  = blockIdx.x * RPB;
    int r   = tid / NQ;          // row within block (0..15)
    int i   = tid - r * NQ;      // qubit index (0..11)

    if (tid < NQ) {
        sm_cr[tid] = cosf(__ldg(&rx[tid]));
        sm_ry[tid] = __ldg(&ry[tid]);
        sm_bf[tid] = __ldg(&b_ffn[tid]);
    }
    if (tid < NQ * NQ) sm_w[tid] = __ldg(&w_ffn[tid]);

    // Stage 16 chunks of 36 float4 each (coalesced within chunk)
    {
        float4* dst = (float4*)sm_x;
#pragma unroll
        for (int k = 0; k < 3; k++) {
            int idx = tid + k * PREP_T;             // 0..575
            int c = idx / 36, j = idx - c * 36;
            const float4* src = (const float4*)(x + (size_t)(s0 + c) * S * NQ);
            dst[c * 36 + j] = __ldg(&src[j]);
        }
    }
    __syncthreads();

    // z for this block's rows and for global rows 0..11
    sm_z[r][i] = sm_cr[i] * cosf(sm_x[r * 144 + i * NQ]);
    if (tid < NQ * NQ) {
        int gi = tid / NQ, gj = tid - gi * NQ;
        sm_z0[tid] = sm_cr[gj] * cosf(__ldg(&x[((size_t)gi * S + gj) * NQ]));
    }
    __syncthreads();

    // attn products
    {
        int w = i;
        float p;
        if (w == 0) {
            p = sm_z[r][1];
            for (int j = 2; j < NQ; j++) p *= sm_z[r][j];
        } else {
            p = sm_z[r][0];
            for (int j = 1; j <= w; j++) p *= sm_z[r][j];
        }
        g_attn[(s0 + r) * NQ + w] = p;
    }
    if (tid < NQ * NQ) {
        int gi = tid / NQ, w = tid - gi * NQ;
        float p;
        if (w == 0) {
            p = sm_z0[gi * NQ + 1];
            for (int j = 2; j < NQ; j++) p *= sm_z0[gi * NQ + j];
        } else {
            p = sm_z0[gi * NQ + 0];
            for (int j = 1; j <= w; j++) p *= sm_z0[gi * NQ + j];
        }
        sm_attn0[gi * NQ + w] = p;
    }
    __syncthreads();

    // tok2 + relu(cos): thread (r, i)
    {
        float g0  = __ldg(&ln1g[0]);
        float bb0 = __ldg(&ln1b[0]);
        float v[NQ];
        float mu = 0.f;
#pragma unroll
        for (int e = 0; e < NQ; e++) {
            v[e] = sm_x[r * 144 + i * NQ + e] + sm_attn0[i * NQ + e];
            mu += v[e];
        }
        mu *= (1.f / 12.f);
        float var = 0.f;
#pragma unroll
        for (int e = 0; e < NQ; e++) { float d = v[e] - mu; var += d * d; }
        var *= (1.f / 12.f);
        float tok2 = (v[0] - mu) * rsqrtf(var + EPSV) * g0 + bb0;
        sm_r[r][i] = fmaxf(cosf(sm_ry[i] + tok2), 0.f);
    }
    __syncthreads();

    // ffn GEMV: thread (r, e)
    {
        int e = i;
        float acc = sm_bf[e];
#pragma unroll
        for (int q = 0; q < NQ; q++)
            acc = fmaf(sm_r[r][q], sm_w[e * NQ + q], acc);
        g_ffn[(s0 + r) * NQ + e] = acc;
    }
}

// -------------------------------------------------------------------------
// k_main: out[b,s,:] = LN2( LN1(x[b,s,:] + attn[s,:]) + ffn[s,:] )
// grid (S/256, B/BPB) = 1024 blocks. Table slice staged once per block,
// x streamed with __ldcs, out with __stcs. 1-deep load pipeline.
// -------------------------------------------------------------------------
__global__ void __launch_bounds__(256) k_main(
    const float* __restrict__ x,
    const float* __restrict__ ln1g, const float* __restrict__ ln1b,
    const float* __restrict__ ln2g, const float* __restrict__ ln2b,
    float* __restrict__ out)
{
    __shared__ __align__(16) float s_attn[256 * NQ];
    __shared__ __align__(16) float s_ffn[256 * NQ];
    __shared__ float s_g1[NQ], s_b1[NQ], s_g2[NQ], s_b2[NQ];

    int s0 = blockIdx.x * 256;
    int b0 = blockIdx.y * BPB;

    {
        const float4* ap = (const float4*)(g_attn + s0 * NQ);
        const float4* fp = (const float4*)(g_ffn + s0 * NQ);
        float4* sa = (float4*)s_attn;
        float4* sf = (float4*)s_ffn;
#pragma unroll
        for (int k = 0; k < 3; k++) {
            int idx = threadIdx.x + k * 256;
            sa[idx] = __ldg(&ap[idx]);
            sf[idx] = __ldg(&fp[idx]);
        }
    }
    if (threadIdx.x < NQ) {
        s_g1[threadIdx.x] = ln1g[threadIdx.x];
        s_b1[threadIdx.x] = ln1b[threadIdx.x];
        s_g2[threadIdx.x] = ln2g[threadIdx.x];
        s_b2[threadIdx.x] = ln2b[threadIdx.x];
    }
    __syncthreads();

    int ls = threadIdx.x;
    float ta[NQ], fa[NQ];
    {
        const float4* av = (const float4*)(s_attn + ls * NQ);
        float4 t0 = av[0], t1 = av[1], t2 = av[2];
        const float4* fv = (const float4*)(s_ffn + ls * NQ);
        float4 f0 = fv[0], f1 = fv[1], f2 = fv[2];
        ta[0]=t0.x; ta[1]=t0.y; ta[2]=t0.z;  ta[3]=t0.w;
        ta[4]=t1.x; ta[5]=t1.y; ta[6]=t1.z;  ta[7]=t1.w;
        ta[8]=t2.x; ta[9]=t2.y; ta[10]=t2.z; ta[11]=t2.w;
        fa[0]=f0.x; fa[1]=f0.y; fa[2]=f0.z;  fa[3]=f0.w;
        fa[4]=f1.x; fa[5]=f1.y; fa[6]=f1.z;  fa[7]=f1.w;
        fa[8]=f2.x; fa[9]=f2.y; fa[10]=f2.z; fa[11]=f2.w;
    }

    size_t row0 = (size_t)b0 * S + s0 + ls;
    const float4* xp = (const float4*)(x + row0 * NQ);

    float4 a0 = __ldcs(xp + 0), a1 = __ldcs(xp + 1), a2 = __ldcs(xp + 2);

#pragma unroll
    for (int it = 0; it < BPB; it++) {
        // prefetch next row (last iter: re-point at current row, values unused;
        // keeps registers defined without extra DRAM traffic)
        int nx = (it + 1 < BPB) ? (it + 1) : it;
        const float4* np = (const float4*)(x + (row0 + (size_t)nx * S) * NQ);
        float4 n0 = __ldcs(np + 0), n1 = __ldcs(np + 1), n2 = __ldcs(np + 2);

        float v[NQ];
        v[0]=a0.x+ta[0]; v[1]=a0.y+ta[1]; v[2] =a0.z+ta[2];  v[3] =a0.w+ta[3];
        v[4]=a1.x+ta[4]; v[5]=a1.y+ta[5]; v[6] =a1.z+ta[6];  v[7] =a1.w+ta[7];
        v[8]=a2.x+ta[8]; v[9]=a2.y+ta[9]; v[10]=a2.z+ta[10]; v[11]=a2.w+ta[11];

        // LN1
        float mu = 0.f;
#pragma unroll
        for (int e = 0; e < NQ; e++) mu += v[e];
        mu *= (1.f / 12.f);
        float var = 0.f;
#pragma unroll
        for (int e = 0; e < NQ; e++) { float d = v[e] - mu; var += d * d; }
        var *= (1.f / 12.f);
        float rs = rsqrtf(var + EPSV);

        float u[NQ];
#pragma unroll
        for (int e = 0; e < NQ; e++)
            u[e] = (v[e] - mu) * rs * s_g1[e] + s_b1[e] + fa[e];

        // LN2
        float mu2 = 0.f;
#pragma unroll
        for (int e = 0; e < NQ; e++) mu2 += u[e];
        mu2 *= (1.f / 12.f);
        float var2 = 0.f;
#pragma unroll
        for (int e = 0; e < NQ; e++) { float d = u[e] - mu2; var2 += d * d; }
        var2 *= (1.f / 12.f);
        float rs2 = rsqrtf(var2 + EPSV);

        float o[NQ];
#pragma unroll
        for (int e = 0; e < NQ; e++)
            o[e] = (u[e] - mu2) * rs2 * s_g2[e] + s_b2[e];

        float4* op = (float4*)(out + (row0 + (size_t)it * S) * NQ);
        __stcs(op + 0, make_float4(o[0], o[1], o[2],  o[3]));
        __stcs(op + 1, make_float4(o[4], o[5], o[6],  o[7]));
        __stcs(op + 2, make_float4(o[8], o[9], o[10], o[11]));

        a0 = n0; a1 = n1; a2 = n2;
    }
}

// -------------------------------------------------------------------------
extern "C" void kernel_launch(void* const* d_in, const int* in_sizes, int n_in,
                              void* d_out, int out_size)
{
    const float* x     = (const float*)d_in[0];
    const float* rx    = (const float*)d_in[1];
    const float* ry    = (const float*)d_in[2];
    const float* w_ffn = (const float*)d_in[3];
    const float* b_ffn = (const float*)d_in[4];
    const float* g1    = (const float*)d_in[5];
    const float* b1    = (const float*)d_in[6];
    const float* g2    = (const float*)d_in[7];
    const float* b2    = (const float*)d_in[8];
    float* out = (float*)d_out;

    k_prep<<<S / RPB, PREP_T>>>(x, rx, ry, w_ffn, b_ffn, g1, b1);

    dim3 grid(S / 256, B / BPB);
    k_main<<<grid, 256>>>(x, g1, b1, g2, b2, out);
}

// round 5
// speedup vs baseline: 2.3000x; 1.0659x over previous
#include <cuda_runtime.h>
#include <math.h>

#define EPSV 1e-5f
#define NQ 12
#define PAD 13               // table row stride in smem (conflict-free: gcd(13,32)=1)
#define B 1024
#define S 1024
#define RPB 16               // rows per block in k_prep
#define PREP_T (RPB * NQ)    // 192 threads
#define BPB 4                // batch rows per block in k_main

__device__ __align__(16) float g_attn[S * NQ];
__device__ __align__(16) float g_ffn[S * NQ];

// -------------------------------------------------------------------------
// k_prep: builds attn + ffn tables. One thread per (row, qubit) pair.
// attn[s,w]: z_i = cos(rx_i)*cos(x[s,i,0]); CNOT chain + ring =>
//   attn[s,w] = prod_{i in S_w} z_i,  S_w = {0..w} (w>=1), S_0 = {1..11}.
// ffn[b,:]:  tok2[b,i] = LN1(x[b,i,:]+attn[i,:])[0];
//   ffn[b,e] = sum_i relu(cos(ry_i+tok2_i)) * w_ffn[e,i] + b_ffn[e]
// -------------------------------------------------------------------------
__global__ void __launch_bounds__(PREP_T) k_prep(
    const float* __restrict__ x,  const float* __restrict__ rx,
    const float* __restrict__ ry, const float* __restrict__ w_ffn,
    const float* __restrict__ b_ffn,
    const float* __restrict__ ln1g, const float* __restrict__ ln1b)
{
    __shared__ __align__(16) float sm_x[RPB * 144];  // x[s0+r, 0:12, 0:12]
    __shared__ float sm_z[RPB][NQ];
    __shared__ float sm_z0[NQ * NQ];
    __shared__ float sm_attn0[NQ * NQ];
    __shared__ float sm_w[NQ * NQ];
    __shared__ float sm_r[RPB][NQ];
    __shared__ float sm_cr[NQ], sm_ry[NQ], sm_bf[NQ];

    int tid = threadIdx.x;
    int s0  = blockIdx.x * RPB;
    int r   = tid / NQ;
    int i   = tid - r * NQ;

    if (tid < NQ) {
        sm_cr[tid] = cosf(__ldg(&rx[tid]));
        sm_ry[tid] = __ldg(&ry[tid]);
        sm_bf[tid] = __ldg(&b_ffn[tid]);
    }
    if (tid < NQ * NQ) sm_w[tid] = __ldg(&w_ffn[tid]);

    {
        float4* dst = (float4*)sm_x;
#pragma unroll
        for (int k = 0; k < 3; k++) {
            int idx = tid + k * PREP_T;             // 0..575
            int c = idx / 36, j = idx - c * 36;
            const float4* src = (const float4*)(x + (size_t)(s0 + c) * S * NQ);
            dst[c * 36 + j] = __ldg(&src[j]);
        }
    }
    __syncthreads();

    sm_z[r][i] = sm_cr[i] * cosf(sm_x[r * 144 + i * NQ]);
    if (tid < NQ * NQ) {
        int gi = tid / NQ, gj = tid - gi * NQ;
        sm_z0[tid] = sm_cr[gj] * cosf(__ldg(&x[((size_t)gi * S + gj) * NQ]));
    }
    __syncthreads();

    {
        int w = i;
        float p;
        if (w == 0) {
            p = sm_z[r][1];
            for (int j = 2; j < NQ; j++) p *= sm_z[r][j];
        } else {
            p = sm_z[r][0];
            for (int j = 1; j <= w; j++) p *= sm_z[r][j];
        }
        g_attn[(s0 + r) * NQ + w] = p;
    }
    if (tid < NQ * NQ) {
        int gi = tid / NQ, w = tid - gi * NQ;
        float p;
        if (w == 0) {
            p = sm_z0[gi * NQ + 1];
            for (int j = 2; j < NQ; j++) p *= sm_z0[gi * NQ + j];
        } else {
            p = sm_z0[gi * NQ + 0];
            for (int j = 1; j <= w; j++) p *= sm_z0[gi * NQ + j];
        }
        sm_attn0[gi * NQ + w] = p;
    }
    __syncthreads();

    {
        float g0  = __ldg(&ln1g[0]);
        float bb0 = __ldg(&ln1b[0]);
        float v[NQ];
        float mu = 0.f;
#pragma unroll
        for (int e = 0; e < NQ; e++) {
            v[e] = sm_x[r * 144 + i * NQ + e] + sm_attn0[i * NQ + e];
            mu += v[e];
        }
        mu *= (1.f / 12.f);
        float var = 0.f;
#pragma unroll
        for (int e = 0; e < NQ; e++) { float d = v[e] - mu; var += d * d; }
        var *= (1.f / 12.f);
        float tok2 = (v[0] - mu) * rsqrtf(var + EPSV) * g0 + bb0;
        sm_r[r][i] = fmaxf(cosf(sm_ry[i] + tok2), 0.f);
    }
    __syncthreads();

    {
        int e = i;
        float acc = sm_bf[e];
#pragma unroll
        for (int q = 0; q < NQ; q++)
            acc = fmaf(sm_r[r][q], sm_w[e * NQ + q], acc);
        g_ffn[(s0 + r) * NQ + e] = acc;
    }
}

// -------------------------------------------------------------------------
// k_main: out[b,s,:] = LN2( LN1(x[b,s,:] + attn[s,:]) + ffn[s,:] )
// grid (S/256, B/BPB). Tables staged once per block into PADDED smem
// (stride 13 -> conflict-free scalar LDS). Minimal-register loop body;
// latency hiding via occupancy (target >=4 blocks/SM).
// -------------------------------------------------------------------------
__global__ void __launch_bounds__(256, 4) k_main(
    const float* __restrict__ x,
    const float* __restrict__ ln1g, const float* __restrict__ ln1b,
    const float* __restrict__ ln2g, const float* __restrict__ ln2b,
    float* __restrict__ out)
{
    __shared__ float s_attn[256 * PAD];
    __shared__ float s_ffn[256 * PAD];
    __shared__ float s_g1[NQ], s_b1[NQ], s_g2[NQ], s_b2[NQ];

    int s0 = blockIdx.x * 256;
    int b0 = blockIdx.y * BPB;

    // Stage tables: 768 float4 per table, scatter into padded layout.
    {
        const float4* ap = (const float4*)(g_attn + s0 * NQ);
        const float4* fp = (const float4*)(g_ffn + s0 * NQ);
#pragma unroll
        for (int k = 0; k < 3; k++) {
            int idx = threadIdx.x + k * 256;    // 0..767
            int row = idx / 3, c = idx - row * 3;
            float4 va = __ldg(&ap[idx]);
            float4 vf = __ldg(&fp[idx]);
            float* da = s_attn + row * PAD + c * 4;
            float* df = s_ffn  + row * PAD + c * 4;
            da[0] = va.x; da[1] = va.y; da[2] = va.z; da[3] = va.w;
            df[0] = vf.x; df[1] = vf.y; df[2] = vf.z; df[3] = vf.w;
        }
    }
    if (threadIdx.x < NQ) {
        s_g1[threadIdx.x] = ln1g[threadIdx.x];
        s_b1[threadIdx.x] = ln1b[threadIdx.x];
        s_g2[threadIdx.x] = ln2g[threadIdx.x];
        s_b2[threadIdx.x] = ln2b[threadIdx.x];
    }
    __syncthreads();

    int ls = threadIdx.x;
    const float* tap = s_attn + ls * PAD;
    const float* fap = s_ffn  + ls * PAD;
    size_t row0 = (size_t)b0 * S + s0 + ls;

#pragma unroll 1
    for (int it = 0; it < BPB; it++) {
        size_t row = row0 + (size_t)it * S;
        const float4* xp = (const float4*)(x + row * NQ);
        float4 a0 = __ldcs(xp + 0), a1 = __ldcs(xp + 1), a2 = __ldcs(xp + 2);

        float v[NQ];
        v[0]=a0.x+tap[0]; v[1]=a0.y+tap[1]; v[2] =a0.z+tap[2];  v[3] =a0.w+tap[3];
        v[4]=a1.x+tap[4]; v[5]=a1.y+tap[5]; v[6] =a1.z+tap[6];  v[7] =a1.w+tap[7];
        v[8]=a2.x+tap[8]; v[9]=a2.y+tap[9]; v[10]=a2.z+tap[10]; v[11]=a2.w+tap[11];

        // LN1
        float mu = 0.f;
#pragma unroll
        for (int e = 0; e < NQ; e++) mu += v[e];
        mu *= (1.f / 12.f);
        float var = 0.f;
#pragma unroll
        for (int e = 0; e < NQ; e++) { float d = v[e] - mu; var += d * d; }
        var *= (1.f / 12.f);
        float rs = rsqrtf(var + EPSV);

        float u[NQ];
#pragma unroll
        for (int e = 0; e < NQ; e++)
            u[e] = (v[e] - mu) * rs * s_g1[e] + s_b1[e] + fap[e];

        // LN2
        float mu2 = 0.f;
#pragma unroll
        for (int e = 0; e < NQ; e++) mu2 += u[e];
        mu2 *= (1.f / 12.f);
        float var2 = 0.f;
#pragma unroll
        for (int e = 0; e < NQ; e++) { float d = u[e] - mu2; var2 += d * d; }
        var2 *= (1.f / 12.f);
        float rs2 = rsqrtf(var2 + EPSV);

        float4* op = (float4*)(out + row * NQ);
        __stcs(op + 0, make_float4((u[0] -mu2)*rs2*s_g2[0] +s_b2[0],
                                   (u[1] -mu2)*rs2*s_g2[1] +s_b2[1],
                                   (u[2] -mu2)*rs2*s_g2[2] +s_b2[2],
                                   (u[3] -mu2)*rs2*s_g2[3] +s_b2[3]));
        __stcs(op + 1, make_float4((u[4] -mu2)*rs2*s_g2[4] +s_b2[4],
                                   (u[5] -mu2)*rs2*s_g2[5] +s_b2[5],
                                   (u[6] -mu2)*rs2*s_g2[6] +s_b2[6],
                                   (u[7] -mu2)*rs2*s_g2[7] +s_b2[7]));
        __stcs(op + 2, make_float4((u[8] -mu2)*rs2*s_g2[8] +s_b2[8],
                                   (u[9] -mu2)*rs2*s_g2[9] +s_b2[9],
                                   (u[10]-mu2)*rs2*s_g2[10]+s_b2[10],
                                   (u[11]-mu2)*rs2*s_g2[11]+s_b2[11]));
    }
}

// -------------------------------------------------------------------------
extern "C" void kernel_launch(void* const* d_in, const int* in_sizes, int n_in,
                              void* d_out, int out_size)
{
    const float* x     = (const float*)d_in[0];
    const float* rx    = (const float*)d_in[1];
    const float* ry    = (const float*)d_in[2];
    const float* w_ffn = (const float*)d_in[3];
    const float* b_ffn = (const float*)d_in[4];
    const float* g1    = (const float*)d_in[5];
    const float* b1    = (const float*)d_in[6];
    const float* g2    = (const float*)d_in[7];
    const float* b2    = (const float*)d_in[8];
    float* out = (float*)d_out;

    k_prep<<<S / RPB, PREP_T>>>(x, rx, ry, w_ffn, b_ffn, g1, b1);

    dim3 grid(S / 256, B / BPB);
    k_main<<<grid, 256>>>(x, g1, b1, g2, b2, out);
}